// round 17
// baseline (speedup 1.0000x reference)
#include <cuda_runtime.h>
#include <cuda_bf16.h>
#include <cuda_fp16.h>
#include <math.h>
#include <stdint.h>

#define D_MODEL 1024
#define D_FF    4096
#define NEXP    8
#define MAXK    4
#define MAXT    8192
#define MAXSLOTS (MAXT*MAXK)
#define PADS     (MAXSLOTS+256)

typedef unsigned long long ull;

// ---------------- static device scratch ----------------
__device__ int   g_counts[NEXP];
__device__ int   g_cursor[NEXP];
__device__ int   g_offsets[NEXP];
__device__ int   g_slot2tok[MAXSLOTS];
__device__ float g_slotw[MAXSLOTS];
__device__ float g_topw[MAXSLOTS];
__device__ int   g_topidx[MAXSLOTS];

__device__ __align__(256) __half g_wghi[(size_t)NEXP*D_FF*D_MODEL];
__device__ __align__(256) __half g_w1hi[(size_t)NEXP*D_FF*D_MODEL];
__device__ __align__(256) __half g_w2hi[(size_t)NEXP*D_MODEL*D_FF];
__device__ __align__(256) __half g_ahi[(size_t)PADS*D_MODEL];
__device__ __align__(256) __half g_hhi[(size_t)PADS*D_FF];

// ---------------- helpers ----------------
__device__ __forceinline__ uint32_t s2u(const void* p) {
    uint32_t a;
    asm("{ .reg .u64 t; cvta.to.shared.u64 t, %1; cvt.u32.u64 %0, t; }"
        : "=r"(a) : "l"(p));
    return a;
}
__device__ __forceinline__ void cpasync16(uint32_t dst, const void* src) {
    asm volatile("cp.async.cg.shared.global [%0], [%1], 16;" :: "r"(dst), "l"(src) : "memory");
}
#define CP_COMMIT() asm volatile("cp.async.commit_group;" ::: "memory")
#define CP_WAIT1()  asm volatile("cp.async.wait_group 1;" ::: "memory")

__device__ __forceinline__ void ldsm4(uint32_t (&r)[4], uint32_t addr) {
    asm volatile("ldmatrix.sync.aligned.m8n8.x4.shared.b16 {%0,%1,%2,%3}, [%4];"
                 : "=r"(r[0]), "=r"(r[1]), "=r"(r[2]), "=r"(r[3]) : "r"(addr));
}
__device__ __forceinline__ void mma16816(float (&c)[4], const uint32_t (&a)[4],
                                         uint32_t b0, uint32_t b1) {
    asm volatile(
        "mma.sync.aligned.m16n8k16.row.col.f32.f16.f16.f32 "
        "{%0,%1,%2,%3}, {%4,%5,%6,%7}, {%8,%9}, {%0,%1,%2,%3};"
        : "+f"(c[0]), "+f"(c[1]), "+f"(c[2]), "+f"(c[3])
        : "r"(a[0]), "r"(a[1]), "r"(a[2]), "r"(a[3]), "r"(b0), "r"(b1));
}

union UH2 { __half2 h; uint32_t u; };
__device__ __forceinline__ uint32_t pack_h2(float a, float b) {
    UH2 v; v.h = __floats2half2_rn(a, b);
    return v.u;
}
__device__ __forceinline__ int clamp_k(const int* kptr) {
    int kk = 2;
    if (kptr) { kk = *kptr; kk = kk < 1 ? 1 : (kk > MAXK ? MAXK : kk); }
    return kk;
}

// ---------------- routing kernels ----------------
__global__ void init_kernel() {
    if (threadIdx.x < NEXP) { g_counts[threadIdx.x] = 0; g_cursor[threadIdx.x] = 0; }
}

__global__ void router_kernel(const float* __restrict__ x,
                              const float* __restrict__ gW,
                              const float* __restrict__ gb,
                              const int* kptr, int T) {
    int gw = (blockIdx.x * blockDim.x + threadIdx.x) >> 5;
    int lane = threadIdx.x & 31;
    if (gw >= T) return;
    const float* xt = x + (size_t)gw * D_MODEL;
    float xr[32];
#pragma unroll
    for (int j = 0; j < 32; j++) xr[j] = xt[lane + j * 32];
    float lg[NEXP];
#pragma unroll
    for (int e = 0; e < NEXP; e++) {
        const float* w = gW + e * D_MODEL;
        float a = 0.f;
#pragma unroll
        for (int j = 0; j < 32; j++) a = fmaf(xr[j], w[lane + j * 32], a);
#pragma unroll
        for (int o = 16; o > 0; o >>= 1) a += __shfl_xor_sync(0xffffffffu, a, o);
        lg[e] = a + gb[e];
    }
    if (lane == 0) {
        int kk = clamp_k(kptr);
        float sc[MAXK]; int sel[MAXK];
        unsigned used = 0;
        for (int j = 0; j < kk; j++) {
            float bv = -3.0e38f; int bi = 0;
            for (int e = 0; e < NEXP; e++)
                if (!((used >> e) & 1u) && lg[e] > bv) { bv = lg[e]; bi = e; }
            used |= 1u << bi; sel[j] = bi; sc[j] = bv;
        }
        float m = sc[0], s = 0.f, p[MAXK];
        for (int j = 0; j < kk; j++) { p[j] = __expf(sc[j] - m); s += p[j]; }
        float inv = 1.f / s;
        for (int j = 0; j < kk; j++) {
            g_topidx[gw * MAXK + j] = sel[j];
            g_topw[gw * MAXK + j] = p[j] * inv;
            atomicAdd(&g_counts[sel[j]], 1);
        }
    }
}

// assign with inline prefix-scan (8 experts); block 0 publishes g_offsets.
__global__ void assign_kernel(const int* kptr, int T) {
    if (blockIdx.x == 0 && threadIdx.x < NEXP) {
        int off = 0;
        for (int ee = 0; ee < (int)threadIdx.x; ee++) off += g_counts[ee];
        g_offsets[threadIdx.x] = off;
    }
    int tid = blockIdx.x * blockDim.x + threadIdx.x;
    if (tid >= T * MAXK) return;
    int t = tid / MAXK, j = tid % MAXK;
    int kk = clamp_k(kptr);
    if (j >= kk) return;
    int e = g_topidx[t * MAXK + j];
    int off = 0;
    for (int ee = 0; ee < e; ee++) off += g_counts[ee];
    int r = atomicAdd(&g_cursor[e], 1);
    int slot = off + r;
    g_slot2tok[slot] = t;
    g_slotw[slot] = g_topw[t * MAXK + j];
}

// ---------------- fused conversion kernel ----------------
__global__ void conv_all_kernel(const float* __restrict__ x,
                                const float* __restrict__ Wg,
                                const float* __restrict__ W1,
                                const float* __restrict__ W2,
                                float* __restrict__ out,
                                int n4out, int T) {
    const int b = blockIdx.x;
    const int tid = threadIdx.x;
    const int NBX = T * 2;
    const int n8 = NEXP * D_FF * D_MODEL / 8;
    if (b < NBX) {
        int slot = b * 2 + (tid >> 7);
        int total = g_offsets[NEXP - 1] + g_counts[NEXP - 1];
        if (slot >= total) return;
        int tok = g_slot2tok[slot];
        int t = tid & 127;
        const float4* s = (const float4*)(x + (size_t)tok * D_MODEL) + t * 2;
        float4 a = s[0], bb = s[1];
        ((uint4*)(g_ahi + (size_t)slot * D_MODEL))[t] =
            make_uint4(pack_h2(a.x, a.y), pack_h2(a.z, a.w),
                       pack_h2(bb.x, bb.y), pack_h2(bb.z, bb.w));
    } else if (b < NBX + 12288) {
        int seg = (b - NBX) >> 12;            // 0=Wg 1=W1 2=W2
        int lb  = (b - NBX) & 4095;
        const float* src = seg == 0 ? Wg : seg == 1 ? W1 : W2;
        __half* dst = seg == 0 ? g_wghi : seg == 1 ? g_w1hi : g_w2hi;
        for (int i = lb * 256 + tid; i < n8; i += 4096 * 256) {
            const float4* s = (const float4*)src + (size_t)i * 2;
            float4 a = s[0], bb = s[1];
            ((uint4*)dst)[i] = make_uint4(pack_h2(a.x, a.y), pack_h2(a.z, a.w),
                                          pack_h2(bb.x, bb.y), pack_h2(bb.z, bb.w));
        }
    } else {
        int lb = b - (NBX + 12288);           // [0, 2048)
        for (int i = lb * 256 + tid; i < n4out; i += 2048 * 256)
            ((float4*)out)[i] = make_float4(0.f, 0.f, 0.f, 0.f);
    }
}

// ---------------- GEMM tiling ----------------
// 64-k chunks, row pitch 144 B (128 data + 16 pad; conflict-free, proven R13).
// 3-stage pipeline, 2 CTAs/SM.
#define PITCH    144
#define G1_STAGE 36864   // A 128*144 + Bg 64*144 + Bv 64*144
#define G2_STAGE 27648   // A 128*144 + B 64*144

// GEMM1 stage: A[128x64]@0, Bg[64x64]@18432, Bv[64x64]@27648
__device__ __forceinline__ void g1_load(
    uint32_t base, const __half* aHi, const __half* bg, const __half* bv,
    int k0, int tid) {
#pragma unroll
    for (int i = 0; i < 8; i++) {          // 2048 chunks of 16B
        int idx = tid + i * 256;
        if (idx < 1024) {                  // A: 128 rows x 8
            int row = idx >> 3, c = idx & 7;
            cpasync16(base + row * PITCH + c * 16,
                      aHi + (size_t)row * D_MODEL + k0 + c * 8);
        } else if (idx < 1536) {           // Bg: 64 rows x 8
            int rem = idx - 1024;
            int row = rem >> 3, c = rem & 7;
            cpasync16(base + 18432 + row * PITCH + c * 16,
                      bg + (size_t)row * D_MODEL + k0 + c * 8);
        } else {                           // Bv
            int rem = idx - 1536;
            int row = rem >> 3, c = rem & 7;
            cpasync16(base + 27648 + row * PITCH + c * 16,
                      bv + (size_t)row * D_MODEL + k0 + c * 8);
        }
    }
}

// ---------------- GEMM1: G = X Wg^T, V = X W1^T, h = silu(G)*V ----------------
// 256 threads, BM=128, BN=64, warp grid 2M x 4N.
__global__ __launch_bounds__(256, 2) void gemm1_mma() {
    const int e = blockIdx.z;
    const int cnt = g_counts[e];
    const int m0 = blockIdx.x * 128;
    if (m0 >= cnt) return;
    const int n0 = blockIdx.y * 64;
    const int offs = g_offsets[e];
    extern __shared__ char smem[];
    uint32_t sb = s2u(smem);
    const int tid = threadIdx.x, lane = tid & 31, wid = tid >> 5;
    const int wM = wid >> 2, wN = wid & 3;

    const __half* aHi = g_ahi + (size_t)(offs + m0) * D_MODEL;
    const size_t wb = (size_t)e * D_FF * D_MODEL + (size_t)n0 * D_MODEL;
    const __half* bg = g_wghi + wb;
    const __half* bv = g_w1hi + wb;

    g1_load(sb + 0 * G1_STAGE, aHi, bg, bv, 0, tid);  CP_COMMIT();
    g1_load(sb + 1 * G1_STAGE, aHi, bg, bv, 64, tid); CP_COMMIT();

    float accG[4][2][4] = {}, accV[4][2][4] = {};
    const int aRow = lane & 15, aK = (lane >> 4) << 3;
    const int bRow = (lane & 7) | ((lane >> 4) << 3);
    const int bK = ((lane >> 3) & 1) << 3;

    const int NCH = D_MODEL / 64;  // 16
    int sj = 0, sp = 2;
    for (int j = 0; j < NCH; j++) {
        CP_WAIT1();
        __syncthreads();
        if (j + 2 < NCH) {
            g1_load(sb + sp * G1_STAGE, aHi, bg, bv, (j + 2) * 64, tid);
            sp = sp == 2 ? 0 : sp + 1;
        }
        CP_COMMIT();
        const uint32_t bA = sb + sj * G1_STAGE;
        sj = sj == 2 ? 0 : sj + 1;
#pragma unroll
        for (int kk = 0; kk < 64; kk += 16) {
            uint32_t ah[4][4];
#pragma unroll
            for (int mt = 0; mt < 4; mt++) {
                uint32_t r = wM * 64 + mt * 16 + aRow;
                ldsm4(ah[mt], bA + r * PITCH + (kk + aK) * 2);
            }
            uint32_t bgf[4], bvf[4];
            {
                uint32_t rN = wN * 16 + bRow;
                uint32_t cb2 = (kk + bK) * 2;
                ldsm4(bgf, bA + 18432 + rN * PITCH + cb2);
                ldsm4(bvf, bA + 27648 + rN * PITCH + cb2);
            }
#pragma unroll
            for (int mt = 0; mt < 4; mt++)
#pragma unroll
                for (int sub = 0; sub < 2; sub++) {
                    mma16816(accG[mt][sub], ah[mt], bgf[sub * 2], bgf[sub * 2 + 1]);
                    mma16816(accV[mt][sub], ah[mt], bvf[sub * 2], bvf[sub * 2 + 1]);
                }
        }
    }

#pragma unroll
    for (int mt = 0; mt < 4; mt++)
#pragma unroll
        for (int half_ = 0; half_ < 2; half_++) {
            int r = m0 + wM * 64 + mt * 16 + (lane >> 2) + half_ * 8;
            if (r < cnt) {
                size_t rowb = (size_t)(offs + r) * D_FF;
#pragma unroll
                for (int sub = 0; sub < 2; sub++) {
                    float gg0 = accG[mt][sub][half_ * 2 + 0];
                    float gg1 = accG[mt][sub][half_ * 2 + 1];
                    float vv0 = accV[mt][sub][half_ * 2 + 0];
                    float vv1 = accV[mt][sub][half_ * 2 + 1];
                    float h0 = gg0 / (1.f + __expf(-gg0)) * vv0;
                    float h1 = gg1 / (1.f + __expf(-gg1)) * vv1;
                    int col = n0 + wN * 16 + sub * 8 + (lane & 3) * 2;
                    *(uint32_t*)(g_hhi + rowb + col) = pack_h2(h0, h1);
                }
            }
        }
}

// GEMM2 stage: A[128x64]@0, B[64x64]@18432
__device__ __forceinline__ void g2_load(
    uint32_t base, const __half* aHi, const __half* bHi, int k0, int tid) {
#pragma unroll
    for (int i = 0; i < 6; i++) {          // 1536 chunks
        int idx = tid + i * 256;
        if (idx < 1024) {                  // A: 128 rows x 8
            int row = idx >> 3, c = idx & 7;
            cpasync16(base + row * PITCH + c * 16,
                      aHi + (size_t)row * D_FF + k0 + c * 8);
        } else {                           // B: 64 rows x 8
            int rem = idx - 1024;
            int row = rem >> 3, c = rem & 7;
            cpasync16(base + 18432 + row * PITCH + c * 16,
                      bHi + (size_t)row * D_FF + k0 + c * 8);
        }
    }
}

// ---------------- GEMM2: y = h W2^T, fused weighted scatter into out ----------------
// 256 threads, BM=128, BN=64, warp grid 4M x 2N (finer grid -> 6.9 waves, small tail).
__global__ __launch_bounds__(256, 2) void gemm2_mma(float* __restrict__ out) {
    const int e = blockIdx.z;
    const int cnt = g_counts[e];
    const int m0 = blockIdx.x * 128;
    if (m0 >= cnt) return;
    const int n0 = blockIdx.y * 64;
    const int offs = g_offsets[e];
    extern __shared__ char smem[];
    uint32_t sb = s2u(smem);
    const int tid = threadIdx.x, lane = tid & 31, wid = tid >> 5;
    const int wM = wid >> 1, wN = wid & 1;

    const __half* aHi = g_hhi + (size_t)(offs + m0) * D_FF;
    const __half* bHi = g_w2hi + (size_t)e * D_MODEL * D_FF + (size_t)n0 * D_FF;

    g2_load(sb + 0 * G2_STAGE, aHi, bHi, 0, tid);  CP_COMMIT();
    g2_load(sb + 1 * G2_STAGE, aHi, bHi, 64, tid); CP_COMMIT();

    float acc[2][4][4] = {};
    const int aRow = lane & 15, aK = (lane >> 4) << 3;
    const int bRow = (lane & 7) | ((lane >> 4) << 3);
    const int bK = ((lane >> 3) & 1) << 3;

    const int NCH = D_FF / 64;  // 64
    int sj = 0, sp = 2;
    for (int j = 0; j < NCH; j++) {
        CP_WAIT1();
        __syncthreads();
        if (j + 2 < NCH) {
            g2_load(sb + sp * G2_STAGE, aHi, bHi, (j + 2) * 64, tid);
            sp = sp == 2 ? 0 : sp + 1;
        }
        CP_COMMIT();
        const uint32_t bA = sb + sj * G2_STAGE;
        sj = sj == 2 ? 0 : sj + 1;
#pragma unroll
        for (int kk = 0; kk < 64; kk += 16) {
            uint32_t ah[2][4];
#pragma unroll
            for (int mt = 0; mt < 2; mt++) {
                uint32_t r = wM * 32 + mt * 16 + aRow;
                ldsm4(ah[mt], bA + r * PITCH + (kk + aK) * 2);
            }
#pragma unroll
            for (int np = 0; np < 2; np++) {
                uint32_t rB = wN * 32 + np * 16 + bRow;
                uint32_t bh[4];
                ldsm4(bh, bA + 18432 + rB * PITCH + (kk + bK) * 2);
#pragma unroll
                for (int mt = 0; mt < 2; mt++)
#pragma unroll
                    for (int sub = 0; sub < 2; sub++)
                        mma16816(acc[mt][np * 2 + sub], ah[mt], bh[sub * 2], bh[sub * 2 + 1]);
            }
        }
    }

    // epilogue: out[tok] += w_slot * y_row (k=2 contributions: deterministic sum)
#pragma unroll
    for (int mt = 0; mt < 2; mt++)
#pragma unroll
        for (int half_ = 0; half_ < 2; half_++) {
            int r = m0 + wM * 32 + mt * 16 + (lane >> 2) + half_ * 8;
            if (r < cnt) {
                int tok = g_slot2tok[offs + r];
                float w = g_slotw[offs + r];
                float* orow = out + (size_t)tok * D_MODEL;
#pragma unroll
                for (int nt = 0; nt < 4; nt++) {
                    int col = n0 + wN * 32 + nt * 8 + (lane & 3) * 2;
                    atomicAdd(&orow[col],     w * acc[mt][nt][half_ * 2 + 0]);
                    atomicAdd(&orow[col + 1], w * acc[mt][nt][half_ * 2 + 1]);
                }
            }
        }
}

// ---------------- launch ----------------
extern "C" void kernel_launch(void* const* d_in, const int* in_sizes, int n_in,
                              void* d_out, int out_size) {
    const float* x  = (const float*)d_in[0];
    const float* gW = (const float*)d_in[1];
    const float* gb = (const float*)d_in[2];
    const float* Wg = (const float*)d_in[3];
    const float* W1 = (const float*)d_in[4];
    const float* W2 = (const float*)d_in[5];
    const int* kptr = (n_in > 6) ? (const int*)d_in[6] : nullptr;
    float* out = (float*)d_out;
    const int T = in_sizes[0] / D_MODEL;

    cudaFuncSetAttribute(gemm1_mma, cudaFuncAttributeMaxDynamicSharedMemorySize, 3 * G1_STAGE);
    cudaFuncSetAttribute(gemm2_mma, cudaFuncAttributeMaxDynamicSharedMemorySize, 3 * G2_STAGE);

    init_kernel<<<1, 32>>>();
    router_kernel<<<(T + 7) / 8, 256>>>(x, gW, gb, kptr, T);
    assign_kernel<<<(T * MAXK + 255) / 256, 256>>>(kptr, T);

    const int nconv = T * 2 + 12288 + 2048;
    conv_all_kernel<<<nconv, 256>>>(x, Wg, W1, W2, out, out_size / 4, T);

    gemm1_mma<<<dim3(32, D_FF / 64, NEXP), 256, 3 * G1_STAGE>>>();
    gemm2_mma<<<dim3(32, D_MODEL / 64, NEXP), 256, 3 * G2_STAGE>>>(out);
}